// round 6
// baseline (speedup 1.0000x reference)
#include <cuda_runtime.h>
#include <cstdint>
#include <cfloat>

#define BB   4
#define CC   64
#define OO   64
#define HH   128
#define WW   128
#define HW   (HH * WW)          // 16384
#define KK   5
#define KK2  (KK * KK)          // 25
#define KROW (CC * KK2)         // 1600
#define PLANE_N (BB * OO)       // 256
#define OUT1 ((size_t)BB * OO * HW)

#define PPT      8
#define TPB      256
#define BLK_PER_PLANE (HW / (TPB * PPT))     // 8
#define VB_TOTAL (BLK_PER_PLANE * PLANE_N)   // 2048
#define NBLK     512                          // 2048/512 = 4 vb per block, all co-resident

// -------- device scratch --------
__device__ float g_s[BB * HW];
__device__ float g_rdn[BB * HW];
__device__ int   g_tap_cnt[OO];
__device__ float g_wsum[OO];
__device__ int   g_tap_k[OO * KROW];
__device__ float g_tap_w[OO * KROW];
__device__ float g_maxv[PLANE_N];
__device__ unsigned g_cnt[4];    // zero-init; self-resetting per run
__device__ unsigned g_done[4];

__device__ __forceinline__ void atomicMaxF(float* a, float v) {
    if (v >= 0.f) atomicMax((int*)a, __float_as_int(v));
    else          atomicMin((unsigned int*)a, __float_as_uint(v));
}

// grid-wide barrier: arrive counter + done counter; last block through done resets both.
__device__ __forceinline__ void grid_barrier(int p) {
    __syncthreads();
    if (threadIdx.x == 0) {
        __threadfence();
        atomicAdd(&g_cnt[p], 1u);
        while (*(volatile unsigned*)&g_cnt[p] < (unsigned)NBLK) __nanosleep(32);
        __threadfence();
        unsigned d = atomicAdd(&g_done[p], 1u) + 1u;
        if (d == (unsigned)NBLK) {
            atomicExch(&g_cnt[p], 0u);
            atomicExch(&g_done[p], 0u);
        }
    }
    __syncthreads();
}

__global__ __launch_bounds__(TPB, 4) void k_fused(const float* __restrict__ x,
                                                  const float* __restrict__ Wl,
                                                  float* __restrict__ out0,
                                                  float* __restrict__ out1,
                                                  float* __restrict__ out2) {
    const int bid = blockIdx.x;
    const int tid = threadIdx.x;

    __shared__ float s_w[64];
    __shared__ int   s_ck[64];
    __shared__ float s_red[TPB / 32];

    // ---------------- Phase A: channel sum (blocks 0..63), sparsify (64..127), maxv init (128)
    if (bid < 64) {
        int t = bid * TPB + tid;                       // quad index, 0..16383
        int b = t / (HW / 4);
        int q = t % (HW / 4);
        const float4* xb = (const float4*)(x + (size_t)b * CC * HW) + q;
        float4 s = make_float4(0.f, 0.f, 0.f, 0.f);
        #pragma unroll
        for (int c = 0; c < CC; c++) {
            float4 v = xb[c * (HW / 4)];
            s.x += v.x; s.y += v.y; s.z += v.z; s.w += v.w;
        }
        ((float4*)g_s)[t] = s;
    } else if (bid < 128) {
        if (tid < 32) {
            int o = bid - 64;
            int lane = tid;
            const float* row = Wl + o * KROW;
            int base = 0;
            float psum = 0.f;
            for (int k0 = 0; k0 < KROW; k0 += 32) {
                int k = k0 + lane;
                float w = row[k];
                psum += w;
                unsigned m = __ballot_sync(0xffffffffu, w != 0.f);
                if (w != 0.f) {
                    int pos = base + __popc(m & ((1u << lane) - 1u));
                    g_tap_k[o * KROW + pos] = k;
                    g_tap_w[o * KROW + pos] = w;
                }
                base += __popc(m);
            }
            #pragma unroll
            for (int off = 16; off; off >>= 1)
                psum += __shfl_xor_sync(0xffffffffu, psum, off);
            if (lane == 0) { g_tap_cnt[o] = base; g_wsum[o] = psum; }
        }
    } else if (bid == 128) {
        g_maxv[tid] = -FLT_MAX;                        // 256 threads = PLANE_N
    }
    grid_barrier(0);

    // ---------------- Phase B: reciprocal denom (blocks 0..255)
    if (bid < 256) {
        int i = bid * TPB + tid;
        int b = i >> 14;
        int p = i & (HW - 1);
        int h = p >> 7, w = p & (WW - 1);
        const float* sb = g_s + b * HW;
        float acc = 0.f;
        #pragma unroll
        for (int dj = -2; dj <= 2; dj++) {
            int hh = h + dj;
            if ((unsigned)hh >= (unsigned)HH) continue;
            #pragma unroll
            for (int dk = -2; dk <= 2; dk++) {
                int ww = w + dk;
                if ((unsigned)ww >= (unsigned)WW) continue;
                acc += sb[hh * WW + ww];
            }
        }
        g_rdn[i] = 1.0f / fmaxf(acc, 5.0f);
    }
    grid_barrier(1);

    // ---------------- Phase C: sparse conv -> out0, plane max of xn1
    for (int vb = bid; vb < VB_TOTAL; vb += NBLK) {
        int bo = vb >> 3;                              // BLK_PER_PLANE = 8
        int chunk = vb & 7;
        int b = bo >> 6, o = bo & 63;

        int cnt = g_tap_cnt[o];
        float inv_ws = 1.f / (1e-10f + g_wsum[o]);
        const float* xb = x + (size_t)b * CC * HW;
        const float* rdn = g_rdn + b * HW;

        int i0 = (chunk * TPB + tid) * PPT;
        int h = i0 >> 7, w0 = i0 & (WW - 1);

        float xl[PPT];
        #pragma unroll
        for (int u = 0; u < PPT; u++) xl[u] = 0.f;

        if (cnt == 1) {
            int k  = g_tap_k[o * KROW];
            float wt = g_tap_w[o * KROW];
            int c = k / KK2, r = k % KK2;
            int hh = h + r / KK - 2;
            int dk = r % KK - 2;
            if ((unsigned)hh < (unsigned)HH) {
                const float* src = xb + c * HW + hh * WW;
                #pragma unroll
                for (int u = 0; u < PPT; u++) {
                    int ww = w0 + u + dk;
                    if ((unsigned)ww < (unsigned)WW) xl[u] = wt * src[ww];
                }
            }
        } else {
            int ncached = min(cnt, 64);
            for (int t = tid; t < ncached; t += TPB) {
                int k = g_tap_k[o * KROW + t];
                int c = k / KK2, r = k % KK2;
                s_ck[t] = (c << 8) | ((r / KK) << 4) | (r % KK);
                s_w[t] = g_tap_w[o * KROW + t];
            }
            __syncthreads();
            for (int t = 0; t < ncached; t++) {
                int pk = s_ck[t];
                float wt = s_w[t];
                int c  = pk >> 8;
                int hh = h + ((pk >> 4) & 15) - 2;
                int dk = (pk & 15) - 2;
                if ((unsigned)hh < (unsigned)HH) {
                    const float* src = xb + c * HW + hh * WW;
                    #pragma unroll
                    for (int u = 0; u < PPT; u++) {
                        int ww = w0 + u + dk;
                        if ((unsigned)ww < (unsigned)WW) xl[u] += wt * src[ww];
                    }
                }
            }
            for (int t = 64; t < cnt; t++) {
                int k = g_tap_k[o * KROW + t];
                float wt = g_tap_w[o * KROW + t];
                int c = k / KK2, r = k % KK2;
                int hh = h + r / KK - 2;
                int dk = r % KK - 2;
                if ((unsigned)hh < (unsigned)HH) {
                    const float* src = xb + c * HW + hh * WW;
                    #pragma unroll
                    for (int u = 0; u < PPT; u++) {
                        int ww = w0 + u + dk;
                        if ((unsigned)ww < (unsigned)WW) xl[u] += wt * src[ww];
                    }
                }
            }
            __syncthreads();
        }

        size_t oidx = (size_t)bo * HW + i0;
        *(float4*)(out0 + oidx)     = make_float4(xl[0], xl[1], xl[2], xl[3]);
        *(float4*)(out0 + oidx + 4) = make_float4(xl[4], xl[5], xl[6], xl[7]);

        float4 r0 = *(const float4*)(rdn + i0);
        float4 r1 = *(const float4*)(rdn + i0 + 4);
        float rd[PPT] = {r0.x, r0.y, r0.z, r0.w, r1.x, r1.y, r1.z, r1.w};
        float mx = -FLT_MAX;
        #pragma unroll
        for (int u = 0; u < PPT; u++) mx = fmaxf(mx, xl[u] * rd[u] * inv_ws);

        #pragma unroll
        for (int off = 16; off; off >>= 1)
            mx = fmaxf(mx, __shfl_xor_sync(0xffffffffu, mx, off));
        if ((tid & 31) == 0) s_red[tid >> 5] = mx;
        __syncthreads();
        if (tid == 0) {
            float v = s_red[0];
            #pragma unroll
            for (int j = 1; j < TPB / 32; j++) v = fmaxf(v, s_red[j]);
            atomicMaxF(&g_maxv[bo], v);
        }
        __syncthreads();
    }
    grid_barrier(2);

    // ---------------- Phase D: finalize (same vb mapping as C -> L1/L2-hot out0)
    for (int vb = bid; vb < VB_TOTAL; vb += NBLK) {
        int bo = vb >> 3;
        int chunk = vb & 7;
        int b = bo >> 6, o = bo & 63;
        float sc = (1.f / (1e-10f + g_wsum[o])) * (1.f / (1e-10f + g_maxv[bo]));
        int i0 = (chunk * TPB + tid) * PPT;
        size_t base = (size_t)bo * HW + i0;
        const float* rdn = g_rdn + b * HW;

        float4 a0 = *(const float4*)(out0 + base);
        float4 a1 = *(const float4*)(out0 + base + 4);
        float4 r0 = *(const float4*)(rdn + i0);
        float4 r1 = *(const float4*)(rdn + i0 + 4);

        float v[PPT] = {a0.x * r0.x * sc, a0.y * r0.y * sc, a0.z * r0.z * sc, a0.w * r0.w * sc,
                        a1.x * r1.x * sc, a1.y * r1.y * sc, a1.z * r1.z * sc, a1.w * r1.w * sc};
        *(float4*)(out1 + base)     = make_float4(v[0], v[1], v[2], v[3]);
        *(float4*)(out1 + base + 4) = make_float4(v[4], v[5], v[6], v[7]);

        float bn[PPT];
        #pragma unroll
        for (int u = 0; u < PPT; u++) bn[u] = (v[u] * v[u] * v[u] >= 0.5f) ? 1.0f : 0.0f;
        *(float4*)(out2 + base)     = make_float4(bn[0], bn[1], bn[2], bn[3]);
        *(float4*)(out2 + base + 4) = make_float4(bn[4], bn[5], bn[6], bn[7]);
    }
}

extern "C" void kernel_launch(void* const* d_in, const int* in_sizes, int n_in,
                              void* d_out, int out_size) {
    const float* x  = (const float*)d_in[0];
    const float* Wl = (const float*)d_in[1];
    float* out  = (float*)d_out;
    k_fused<<<NBLK, TPB>>>(x, Wl, out, out + OUT1, out + 2 * OUT1);
}

// round 7
// speedup vs baseline: 1.3288x; 1.3288x over previous
#include <cuda_runtime.h>
#include <cstdint>
#include <cfloat>

#define BB   4
#define CC   64
#define OO   64
#define HH   128
#define WW   128
#define HW   (HH * WW)          // 16384
#define KK   5
#define KK2  (KK * KK)          // 25
#define KROW (CC * KK2)         // 1600
#define PLANE_N (BB * OO)       // 256
#define OUT1 ((size_t)BB * OO * HW)

#define TPB 256

// -------- device scratch --------
__device__ float g_s[BB * HW];
__device__ float g_rdn[BB * HW];
__device__ int   g_tap_cnt[OO];
__device__ float g_wsum[OO];
__device__ int   g_tap_k[OO * KROW];
__device__ float g_tap_w[OO * KROW];
__device__ float g_maxv[PLANE_N];

__device__ __forceinline__ void atomicMaxF(float* a, float v) {
    if (v >= 0.f) atomicMax((int*)a, __float_as_int(v));
    else          atomicMin((unsigned int*)a, __float_as_uint(v));
}

// -------- 1) channel sum (float4/thread) + g_maxv init --------
__global__ void k_chansum(const float* __restrict__ x) {
    int t = blockIdx.x * blockDim.x + threadIdx.x;   // quad index
    if (blockIdx.x == 0) g_maxv[threadIdx.x] = -FLT_MAX;
    int b = t / (HW / 4);
    int q = t % (HW / 4);
    const float4* xb = (const float4*)(x + (size_t)b * CC * HW) + q;
    float4 s = make_float4(0.f, 0.f, 0.f, 0.f);
    #pragma unroll
    for (int c = 0; c < CC; c++) {
        float4 v = xb[c * (HW / 4)];
        s.x += v.x; s.y += v.y; s.z += v.z; s.w += v.w;
    }
    ((float4*)g_s)[t] = s;
}

// -------- 2) prep: blocks [0,256) reciprocal denom; [256,320) sparsify W --------
#define DENOM_BLOCKS (BB * HW / TPB)   // 256
__global__ void k_prep(const float* __restrict__ Wl) {
    if (blockIdx.x < DENOM_BLOCKS) {
        int i = blockIdx.x * TPB + threadIdx.x;
        int b = i >> 14;
        int p = i & (HW - 1);
        int h = p >> 7, w = p & (WW - 1);
        const float* sb = g_s + b * HW;
        float acc = 0.f;
        #pragma unroll
        for (int dj = -2; dj <= 2; dj++) {
            int hh = h + dj;
            if ((unsigned)hh >= (unsigned)HH) continue;
            #pragma unroll
            for (int dk = -2; dk <= 2; dk++) {
                int ww = w + dk;
                if ((unsigned)ww >= (unsigned)WW) continue;
                acc += sb[hh * WW + ww];
            }
        }
        g_rdn[i] = 1.0f / fmaxf(acc, 5.0f);
        return;
    }
    if (threadIdx.x >= 32) return;
    int o = blockIdx.x - DENOM_BLOCKS;
    int lane = threadIdx.x;
    const float* row = Wl + o * KROW;
    int base = 0;
    float psum = 0.f;
    for (int k0 = 0; k0 < KROW; k0 += 32) {
        int k = k0 + lane;
        float w = row[k];
        psum += w;
        unsigned m = __ballot_sync(0xffffffffu, w != 0.f);
        if (w != 0.f) {
            int pos = base + __popc(m & ((1u << lane) - 1u));
            g_tap_k[o * KROW + pos] = k;
            g_tap_w[o * KROW + pos] = w;
        }
        base += __popc(m);
    }
    #pragma unroll
    for (int off = 16; off; off >>= 1)
        psum += __shfl_xor_sync(0xffffffffu, psum, off);
    if (lane == 0) { g_tap_cnt[o] = base; g_wsum[o] = psum; }
}

// -------- 3) main: sparse conv -> out0, xn1 -> out1, plane max. PPT=4 --------
__global__ __launch_bounds__(TPB) void k_main(const float* __restrict__ x,
                                              float* __restrict__ out0,
                                              float* __restrict__ out1) {
    int bo = blockIdx.y;
    int b = bo >> 6, o = bo & 63;

    __shared__ float s_w[64];
    __shared__ int   s_ck[64];
    __shared__ float s_red[TPB / 32];

    int cnt = g_tap_cnt[o];              // uniform load
    float inv_ws = 1.f / (1e-10f + g_wsum[o]);
    const float* xb = x + (size_t)b * CC * HW;
    const float* rdn = g_rdn + b * HW;

    int i0 = (blockIdx.x * TPB + threadIdx.x) * 4;
    int h = i0 >> 7, w0 = i0 & (WW - 1);

    float xl0 = 0.f, xl1 = 0.f, xl2 = 0.f, xl3 = 0.f;

    if (cnt == 1) {
        // uniform single tap
        int k  = g_tap_k[o * KROW];
        float wt = g_tap_w[o * KROW];
        int c = k / KK2, r = k % KK2;
        int dj = r / KK - 2, dk = r % KK - 2;
        int hh = h + dj;
        if ((unsigned)hh < (unsigned)HH) {
            const float* src = xb + c * HW + hh * WW;
            if (dk == 0) {
                // 16B-aligned contiguous quad: one vector load
                float4 v = *(const float4*)(src + w0);
                xl0 = wt * v.x; xl1 = wt * v.y; xl2 = wt * v.z; xl3 = wt * v.w;
            } else {
                int ww;
                ww = w0 + 0 + dk; if ((unsigned)ww < (unsigned)WW) xl0 = wt * src[ww];
                ww = w0 + 1 + dk; if ((unsigned)ww < (unsigned)WW) xl1 = wt * src[ww];
                ww = w0 + 2 + dk; if ((unsigned)ww < (unsigned)WW) xl2 = wt * src[ww];
                ww = w0 + 3 + dk; if ((unsigned)ww < (unsigned)WW) xl3 = wt * src[ww];
            }
        }
    } else {
        int ncached = min(cnt, 64);
        for (int t = threadIdx.x; t < ncached; t += TPB) {
            int k = g_tap_k[o * KROW + t];
            int c = k / KK2, r = k % KK2;
            s_ck[t] = (c << 8) | ((r / KK) << 4) | (r % KK);
            s_w[t] = g_tap_w[o * KROW + t];
        }
        __syncthreads();
        for (int t = 0; t < ncached; t++) {
            int pk = s_ck[t];
            float wt = s_w[t];
            int c  = pk >> 8;
            int hh = h + ((pk >> 4) & 15) - 2;
            int dk = (pk & 15) - 2;
            if ((unsigned)hh < (unsigned)HH) {
                const float* src = xb + c * HW + hh * WW;
                int ww;
                ww = w0 + 0 + dk; if ((unsigned)ww < (unsigned)WW) xl0 += wt * src[ww];
                ww = w0 + 1 + dk; if ((unsigned)ww < (unsigned)WW) xl1 += wt * src[ww];
                ww = w0 + 2 + dk; if ((unsigned)ww < (unsigned)WW) xl2 += wt * src[ww];
                ww = w0 + 3 + dk; if ((unsigned)ww < (unsigned)WW) xl3 += wt * src[ww];
            }
        }
        for (int t = 64; t < cnt; t++) {       // rare spill
            int k = g_tap_k[o * KROW + t];
            float wt = g_tap_w[o * KROW + t];
            int c = k / KK2, r = k % KK2;
            int hh = h + r / KK - 2;
            int dk = r % KK - 2;
            if ((unsigned)hh < (unsigned)HH) {
                const float* src = xb + c * HW + hh * WW;
                int ww;
                ww = w0 + 0 + dk; if ((unsigned)ww < (unsigned)WW) xl0 += wt * src[ww];
                ww = w0 + 1 + dk; if ((unsigned)ww < (unsigned)WW) xl1 += wt * src[ww];
                ww = w0 + 2 + dk; if ((unsigned)ww < (unsigned)WW) xl2 += wt * src[ww];
                ww = w0 + 3 + dk; if ((unsigned)ww < (unsigned)WW) xl3 += wt * src[ww];
            }
        }
        __syncthreads();
    }

    size_t oidx = (size_t)bo * HW + i0;
    *(float4*)(out0 + oidx) = make_float4(xl0, xl1, xl2, xl3);

    float4 r0 = *(const float4*)(rdn + i0);
    float a0 = xl0 * r0.x * inv_ws;
    float a1 = xl1 * r0.y * inv_ws;
    float a2 = xl2 * r0.z * inv_ws;
    float a3 = xl3 * r0.w * inv_ws;
    *(float4*)(out1 + oidx) = make_float4(a0, a1, a2, a3);

    float mx = fmaxf(fmaxf(a0, a1), fmaxf(a2, a3));
    #pragma unroll
    for (int off = 16; off; off >>= 1)
        mx = fmaxf(mx, __shfl_xor_sync(0xffffffffu, mx, off));
    if ((threadIdx.x & 31) == 0) s_red[threadIdx.x >> 5] = mx;
    __syncthreads();
    if (threadIdx.x == 0) {
        float v = s_red[0];
        #pragma unroll
        for (int j = 1; j < TPB / 32; j++) v = fmaxf(v, s_red[j]);
        atomicMaxF(&g_maxv[bo], v);
    }
}

// -------- 4) finalize: rescale out1 in place, emit out2. PPT=8 --------
__global__ __launch_bounds__(TPB) void k_final(float* __restrict__ out1,
                                               float* __restrict__ out2) {
    int bo = blockIdx.y;
    float r = 1.0f / (1e-10f + g_maxv[bo]);
    size_t base = (size_t)bo * HW + (size_t)(blockIdx.x * TPB + threadIdx.x) * 8;
    float4 v0 = *(float4*)(out1 + base);
    float4 v1 = *(float4*)(out1 + base + 4);
    v0.x *= r; v0.y *= r; v0.z *= r; v0.w *= r;
    v1.x *= r; v1.y *= r; v1.z *= r; v1.w *= r;
    *(float4*)(out1 + base)     = v0;
    *(float4*)(out1 + base + 4) = v1;
    float4 b0, b1;
    b0.x = (v0.x * v0.x * v0.x >= 0.5f) ? 1.0f : 0.0f;
    b0.y = (v0.y * v0.y * v0.y >= 0.5f) ? 1.0f : 0.0f;
    b0.z = (v0.z * v0.z * v0.z >= 0.5f) ? 1.0f : 0.0f;
    b0.w = (v0.w * v0.w * v0.w >= 0.5f) ? 1.0f : 0.0f;
    b1.x = (v1.x * v1.x * v1.x >= 0.5f) ? 1.0f : 0.0f;
    b1.y = (v1.y * v1.y * v1.y >= 0.5f) ? 1.0f : 0.0f;
    b1.z = (v1.z * v1.z * v1.z >= 0.5f) ? 1.0f : 0.0f;
    b1.w = (v1.w * v1.w * v1.w >= 0.5f) ? 1.0f : 0.0f;
    *(float4*)(out2 + base)     = b0;
    *(float4*)(out2 + base + 4) = b1;
}

extern "C" void kernel_launch(void* const* d_in, const int* in_sizes, int n_in,
                              void* d_out, int out_size) {
    const float* x  = (const float*)d_in[0];
    const float* Wl = (const float*)d_in[1];
    float* out  = (float*)d_out;
    float* out0 = out;
    float* out1 = out + OUT1;
    float* out2 = out + 2 * OUT1;

    k_chansum<<<BB * HW / 4 / TPB, TPB>>>(x);
    k_prep<<<DENOM_BLOCKS + OO, TPB>>>(Wl);
    dim3 gmain(HW / (TPB * 4), PLANE_N);       // (16, 256)
    k_main<<<gmain, TPB>>>(x, out0, out1);
    dim3 gfin(HW / (TPB * 8), PLANE_N);        // (8, 256)
    k_final<<<gfin, TPB>>>(out1, out2);
}